// round 1
// baseline (speedup 1.0000x reference)
#include <cuda_runtime.h>
#include <math.h>

// Shapes fixed by the problem instance
#define BH   32          // B*H = 2*16
#define LEN  4096        // sequence length
#define DIM  64          // head dim
#define MF   64          // feature dim (M)
#define CHK  64          // our chunk size (math is chunk-invariant)
#define NC   (LEN/CHK)   // 64 chunks

#define DN     0.35355339059327373f  // 64^-0.25
#define RATIO  0.125f                // 64^-0.5
#define EPSV   1e-4f

// Scratch (device globals: allocation-free rule)
__device__ float g_qp[BH*LEN*MF];      // positive features of q
__device__ float g_kp[BH*LEN*MF];      // k dash, then positive features of k (in place)
__device__ float g_kdiag[BH*LEN];      // 0.5*|k|^2*dn^2 per token
__device__ float g_bhmax[BH];          // per-(b,h) max of k dash
__device__ float g_kv[BH*NC*MF*DIM];   // per-chunk KV, then exclusive prefix (in place)
__device__ float g_ks[BH*NC*MF];       // per-chunk K-sum, then exclusive prefix

__device__ __forceinline__ void atomicMaxFloat(float* addr, float val) {
    int* ia = (int*)addr;
    int old = *ia;
    while (__int_as_float(old) < val) {
        int assumed = old;
        old = atomicCAS(ia, assumed, __float_as_int(val));
        if (old == assumed) break;
    }
}

__global__ void init_kernel() {
    if (threadIdx.x < BH) g_bhmax[threadIdx.x] = -INFINITY;
}

// ---------------------------------------------------------------------------
// Feature kernel: 16 rows per block, 256 threads.
// dash[m] = (x_row . proj[:,m]) * dn ; diag = 0.5*|x|^2*dn^2
// IS_Q: subtract per-row max, exp, write qp.  else: store dash/diag, atomic bh-max.
// ---------------------------------------------------------------------------
template<bool IS_Q>
__global__ void feat_kernel(const float* __restrict__ x, const float* __restrict__ proj) {
    __shared__ float proj_s[DIM][MF];   // 16KB
    __shared__ float x_s[16][DIM];      // 4KB
    __shared__ float dash_s[16][MF];    // 4KB
    __shared__ float rmax_s[16];
    __shared__ float diag_s[16];

    const int tid = threadIdx.x;
    const int rowBase = blockIdx.x * 16;

    for (int i = tid; i < DIM*MF; i += 256) proj_s[i/MF][i%MF] = proj[i];
    for (int i = tid; i < 16*DIM; i += 256) x_s[i/DIM][i%DIM] = x[(size_t)rowBase*DIM + i];
    __syncthreads();

    const int mcol = tid & 63;
    const int rg   = tid >> 6;    // 0..3 -> rows rg*4 .. rg*4+3

    float a0=0.f, a1=0.f, a2=0.f, a3=0.f;
    #pragma unroll
    for (int d0 = 0; d0 < DIM; ++d0) {
        const float p = proj_s[d0][mcol];
        a0 += x_s[rg*4+0][d0] * p;
        a1 += x_s[rg*4+1][d0] * p;
        a2 += x_s[rg*4+2][d0] * p;
        a3 += x_s[rg*4+3][d0] * p;
    }
    dash_s[rg*4+0][mcol] = a0 * DN;
    dash_s[rg*4+1][mcol] = a1 * DN;
    dash_s[rg*4+2][mcol] = a2 * DN;
    dash_s[rg*4+3][mcol] = a3 * DN;
    __syncthreads();

    const int wid = tid >> 5, lane = tid & 31;
    for (int rr = wid; rr < 16; rr += 8) {
        float mx = fmaxf(dash_s[rr][lane], dash_s[rr][lane+32]);
        const float qa = x_s[rr][lane], qb = x_s[rr][lane+32];
        float dg = qa*qa + qb*qb;
        #pragma unroll
        for (int off = 16; off; off >>= 1) {
            mx = fmaxf(mx, __shfl_xor_sync(0xffffffffu, mx, off));
            dg += __shfl_xor_sync(0xffffffffu, dg, off);
        }
        if (lane == 0) { rmax_s[rr] = mx; diag_s[rr] = 0.5f * dg * DN * DN; }
    }
    __syncthreads();

    if (IS_Q) {
        #pragma unroll
        for (int i = 0; i < 4; ++i) {
            const int rr = rg*4 + i;
            const float val = RATIO * (expf(dash_s[rr][mcol] - diag_s[rr] - rmax_s[rr]) + EPSV);
            g_qp[(size_t)(rowBase + rr)*MF + mcol] = val;
        }
    } else {
        #pragma unroll
        for (int i = 0; i < 4; ++i) {
            const int rr = rg*4 + i;
            g_kp[(size_t)(rowBase + rr)*MF + mcol] = dash_s[rr][mcol];
        }
        if (tid < 16) g_kdiag[rowBase + tid] = diag_s[tid];
        if (tid == 0) {
            float bm = rmax_s[0];
            #pragma unroll
            for (int r = 1; r < 16; ++r) bm = fmaxf(bm, rmax_s[r]);
            atomicMaxFloat(&g_bhmax[rowBase / LEN], bm);
        }
    }
}

// k features: exp pass after global bh max known. Each thread: 4 consecutive elems.
__global__ void kexp_kernel() {
    const int idx = blockIdx.x * blockDim.x + threadIdx.x;
    const int base = idx * 4;                       // never crosses a row (MF=64 % 4 == 0)
    const int row = base >> 6;                      // / MF
    const float diag = g_kdiag[row];
    const float mx = g_bhmax[row / LEN];
    float4 dv = *(float4*)&g_kp[base];
    dv.x = RATIO * (expf(dv.x - diag - mx) + EPSV);
    dv.y = RATIO * (expf(dv.y - diag - mx) + EPSV);
    dv.z = RATIO * (expf(dv.z - diag - mx) + EPSV);
    dv.w = RATIO * (expf(dv.w - diag - mx) + EPSV);
    *(float4*)&g_kp[base] = dv;
}

// ---------------------------------------------------------------------------
// Per-chunk KV state: kv[m][d] = sum_j kp[j][m]*v[j][d];  ks[m] = sum_j kp[j][m]
// One block per (bh, chunk). 256 threads, 4x4 register tile.
// ---------------------------------------------------------------------------
__global__ void chunkkv_kernel(const float* __restrict__ v) {
    __shared__ float k_s[CHK][MF+1];
    __shared__ float v_s[CHK][DIM+1];
    const int tid = threadIdx.x;
    const int bh = blockIdx.x / NC, c = blockIdx.x % NC;
    const float* kpp = g_kp + ((size_t)bh*LEN + (size_t)c*CHK) * MF;
    const float* vp  = v    + ((size_t)bh*LEN + (size_t)c*CHK) * DIM;
    for (int i = tid; i < CHK*MF;  i += 256) k_s[i/MF][i%MF]   = kpp[i];
    for (int i = tid; i < CHK*DIM; i += 256) v_s[i/DIM][i%DIM] = vp[i];
    __syncthreads();

    const int tm = tid >> 4, td = tid & 15;
    float acc[4][4] = {};
    for (int j = 0; j < CHK; ++j) {
        float kk[4], vv[4];
        #pragma unroll
        for (int i = 0; i < 4; ++i) kk[i] = k_s[j][tm*4 + i];
        #pragma unroll
        for (int l = 0; l < 4; ++l) vv[l] = v_s[j][td*4 + l];
        #pragma unroll
        for (int i = 0; i < 4; ++i)
            #pragma unroll
            for (int l = 0; l < 4; ++l)
                acc[i][l] += kk[i] * vv[l];
    }
    const size_t ob = (size_t)blockIdx.x * MF * DIM;
    #pragma unroll
    for (int i = 0; i < 4; ++i)
        #pragma unroll
        for (int l = 0; l < 4; ++l)
            g_kv[ob + (size_t)(tm*4+i)*DIM + td*4 + l] = acc[i][l];

    if (tid < MF) {
        float s = 0.f;
        for (int j = 0; j < CHK; ++j) s += k_s[j][tid];
        g_ks[(size_t)blockIdx.x * MF + tid] = s;
    }
}

// Exclusive prefix scan over chunks (in place). One block per bh.
__global__ void scan_kernel() {
    const int bh = blockIdx.x, tid = threadIdx.x;
    for (int e = tid; e < MF*DIM; e += 512) {
        size_t base = (size_t)bh * NC * MF * DIM + e;
        float run = 0.f;
        for (int c = 0; c < NC; ++c) {
            const size_t idx = base + (size_t)c * MF * DIM;
            const float t = g_kv[idx];
            g_kv[idx] = run;
            run += t;
        }
    }
    for (int e = tid; e < MF; e += 512) {
        size_t base = (size_t)bh * NC * MF + e;
        float run = 0.f;
        for (int c = 0; c < NC; ++c) {
            const size_t idx = base + (size_t)c * MF;
            const float t = g_ks[idx];
            g_ks[idx] = run;
            run += t;
        }
    }
}

// ---------------------------------------------------------------------------
// Output: S = Qc Kc^T (causal mask), out = (S Vc + Qc KVprev) / (rowsum(S) + Qc.KSprev)
// One block per (bh, chunk). 256 threads. Dynamic smem ~82KB.
// ---------------------------------------------------------------------------
__global__ void attn_kernel(const float* __restrict__ v, float* __restrict__ out) {
    extern __shared__ float sm[];
    float* qT  = sm;                       // [MF][CHK+1] (transposed)
    float* kT  = qT  + MF*(CHK+1);         // [MF][CHK+1] (transposed)
    float* vs  = kT  + MF*(CHK+1);         // [CHK][DIM+1]
    float* Ss  = vs  + CHK*(DIM+1);        // [CHK][CHK+1]
    float* kvp = Ss  + CHK*(CHK+1);        // [MF][DIM+1]
    float* ksp = kvp + MF*(DIM+1);         // [MF]
    float* den = ksp + MF;                 // [CHK]

    const int tid = threadIdx.x;
    const int bh = blockIdx.x / NC, c = blockIdx.x % NC;

    const size_t fb = ((size_t)bh*LEN + (size_t)c*CHK) * MF;
    for (int i = tid; i < CHK*MF; i += 256) {
        const int r = i / MF, m = i % MF;
        qT[m*(CHK+1) + r] = g_qp[fb + i];
        kT[m*(CHK+1) + r] = g_kp[fb + i];
    }
    const size_t vb = ((size_t)bh*LEN + (size_t)c*CHK) * DIM;
    for (int i = tid; i < CHK*DIM; i += 256) vs[(i/DIM)*(DIM+1) + (i%DIM)] = v[vb + i];
    const size_t kb = (size_t)blockIdx.x * MF * DIM;
    for (int i = tid; i < MF*DIM; i += 256) kvp[(i/DIM)*(DIM+1) + (i%DIM)] = g_kv[kb + i];
    if (tid < MF) ksp[tid] = g_ks[(size_t)blockIdx.x * MF + tid];
    __syncthreads();

    const int tr = tid >> 4, tc = tid & 15;

    // Stage 1: masked scores S
    {
        float acc[4][4] = {};
        for (int m = 0; m < MF; ++m) {
            float qv[4], kv4[4];
            #pragma unroll
            for (int i = 0; i < 4; ++i) qv[i]  = qT[m*(CHK+1) + tr*4 + i];
            #pragma unroll
            for (int j = 0; j < 4; ++j) kv4[j] = kT[m*(CHK+1) + tc*4 + j];
            #pragma unroll
            for (int i = 0; i < 4; ++i)
                #pragma unroll
                for (int j = 0; j < 4; ++j)
                    acc[i][j] += qv[i] * kv4[j];
        }
        #pragma unroll
        for (int i = 0; i < 4; ++i)
            #pragma unroll
            for (int j = 0; j < 4; ++j) {
                const int r = tr*4 + i, cc = tc*4 + j;
                Ss[r*(CHK+1) + cc] = (cc <= r) ? acc[i][j] : 0.f;
            }
    }
    __syncthreads();

    // Denominators
    if (tid < CHK) {
        float ds = 0.f;
        for (int j = 0; j < CHK; ++j) ds += Ss[tid*(CHK+1) + j];
        for (int m = 0; m < MF; ++m)  ds += qT[m*(CHK+1) + tid] * ksp[m];
        den[tid] = ds;
    }
    __syncthreads();

    // Stage 2: intra (S @ V) + inter (Q @ KVprev)
    float o[4][4] = {};
    for (int j = 0; j < CHK; ++j) {
        float sv[4], vv4[4];
        #pragma unroll
        for (int i = 0; i < 4; ++i) sv[i]  = Ss[(tr*4+i)*(CHK+1) + j];
        #pragma unroll
        for (int l = 0; l < 4; ++l) vv4[l] = vs[j*(DIM+1) + tc*4 + l];
        #pragma unroll
        for (int i = 0; i < 4; ++i)
            #pragma unroll
            for (int l = 0; l < 4; ++l)
                o[i][l] += sv[i] * vv4[l];
    }
    for (int m = 0; m < MF; ++m) {
        float qv[4], kv4[4];
        #pragma unroll
        for (int i = 0; i < 4; ++i) qv[i]  = qT[m*(CHK+1) + tr*4 + i];
        #pragma unroll
        for (int l = 0; l < 4; ++l) kv4[l] = kvp[m*(DIM+1) + tc*4 + l];
        #pragma unroll
        for (int i = 0; i < 4; ++i)
            #pragma unroll
            for (int l = 0; l < 4; ++l)
                o[i][l] += qv[i] * kv4[l];
    }

    const size_t ob = ((size_t)bh*LEN + (size_t)c*CHK) * DIM;
    #pragma unroll
    for (int i = 0; i < 4; ++i) {
        const float inv = 1.f / den[tr*4 + i];
        #pragma unroll
        for (int l = 0; l < 4; ++l)
            out[ob + (size_t)(tr*4+i)*DIM + tc*4 + l] = o[i][l] * inv;
    }
}

// ---------------------------------------------------------------------------

extern "C" void kernel_launch(void* const* d_in, const int* in_sizes, int n_in,
                              void* d_out, int out_size) {
    const float* q    = (const float*)d_in[0];
    const float* k    = (const float*)d_in[1];
    const float* v    = (const float*)d_in[2];
    const float* proj = (const float*)d_in[3];
    // d_in[4] = chunk_size (ignored: the chunked formulation is exact for any chunk)
    float* out = (float*)d_out;

    const int ATTN_SMEM = (5 * MF * (CHK+1) + MF + CHK) * (int)sizeof(float); // 83712 B
    cudaFuncSetAttribute(attn_kernel, cudaFuncAttributeMaxDynamicSharedMemorySize, ATTN_SMEM);

    init_kernel<<<1, 32>>>();
    feat_kernel<true ><<<BH*LEN/16, 256>>>(q, proj);
    feat_kernel<false><<<BH*LEN/16, 256>>>(k, proj);
    kexp_kernel<<<BH*LEN*MF/1024, 256>>>();
    chunkkv_kernel<<<BH*NC, 256>>>(v);
    scan_kernel<<<BH, 512>>>();
    attn_kernel<<<BH*NC, 256, ATTN_SMEM>>>(v, out);
}

// round 2
// speedup vs baseline: 1.9721x; 1.9721x over previous
#include <cuda_runtime.h>
#include <math.h>

#define BH   32
#define LEN  4096
#define DIM  64
#define MF   64
#define CHK  64
#define NC   (LEN/CHK)     // 64

#define DN     0.35355339059327373f  // 64^-0.25
#define RATIO  0.125f                // 64^-0.5
#define EPSV   1e-4f

#define SP   68                      // padded smem row stride (floats)
#define TILE (64*SP)                 // 4352 floats

// Scratch (device globals: allocation-free rule)
__device__ float g_qp[BH*LEN*MF];      // positive features of q
__device__ float g_kp[BH*LEN*MF];      // k dash (raw, exp applied at use)
__device__ float g_kdiag[BH*LEN];      // 0.5*|k|^2*dn^2 per token
__device__ float g_bhmax[BH];          // per-(b,h) max of k dash
__device__ float g_kv[BH*NC*MF*DIM];   // per-chunk KV -> exclusive prefix (in place)
__device__ float g_ks[BH*NC*MF];       // per-chunk K-sum -> exclusive prefix

__device__ __forceinline__ void atomicMaxFloat(float* addr, float val) {
    int* ia = (int*)addr;
    int old = *ia;
    while (__int_as_float(old) < val) {
        int assumed = old;
        old = atomicCAS(ia, assumed, __float_as_int(val));
        if (old == assumed) break;
    }
}

__global__ void init_kernel() {
    if (threadIdx.x < BH) g_bhmax[threadIdx.x] = -INFINITY;
}

// 16-FMA outer-product micro-tile: rows from a (float4), cols from b (float4)
#define FMA16(acc, a, b)                                                      \
    acc[0][0] += a.x*b.x; acc[0][1] += a.x*b.y; acc[0][2] += a.x*b.z; acc[0][3] += a.x*b.w; \
    acc[1][0] += a.y*b.x; acc[1][1] += a.y*b.y; acc[1][2] += a.y*b.z; acc[1][3] += a.y*b.w; \
    acc[2][0] += a.z*b.x; acc[2][1] += a.z*b.y; acc[2][2] += a.z*b.z; acc[2][3] += a.z*b.w; \
    acc[3][0] += a.w*b.x; acc[3][1] += a.w*b.y; acc[3][2] += a.w*b.z; acc[3][3] += a.w*b.w;

// ---------------------------------------------------------------------------
// Feature kernel: 64 rows per block, 256 threads, 4x4 register tile.
// dash = (X @ P) * dn ; diag = 0.5*|x|^2*dn^2
// IS_Q: per-row max -> exp -> g_qp.   else: raw dash -> g_kp, diag, atomic bh max.
// ---------------------------------------------------------------------------
template<bool IS_Q>
__global__ void feat_kernel(const float* __restrict__ x, const float* __restrict__ proj) {
    __shared__ float xT[TILE];   // [d][row], stride SP
    __shared__ float ps[TILE];   // [d][m],   stride SP
    __shared__ float wmax[16];

    const int tid = threadIdx.x;
    const int rowBase = blockIdx.x * 64;
    const int bh = blockIdx.x >> 6;          // 64 blocks per (b,h)

    // fill proj [d][m]
    for (int i4 = tid; i4 < DIM*MF/4; i4 += 256) {
        float4 p = ((const float4*)proj)[i4];
        int d = i4 >> 4, m0 = (i4 & 15) * 4;
        *(float4*)&ps[d*SP + m0] = p;
    }
    // fill x transposed: xT[d][row]
    {
        const float4* xg = (const float4*)(x + (size_t)rowBase * DIM);
        for (int i4 = tid; i4 < 64*DIM/4; i4 += 256) {
            float4 xv = xg[i4];
            int r = i4 >> 4, d0 = (i4 & 15) * 4;
            xT[(d0+0)*SP + r] = xv.x;
            xT[(d0+1)*SP + r] = xv.y;
            xT[(d0+2)*SP + r] = xv.z;
            xT[(d0+3)*SP + r] = xv.w;
        }
    }
    __syncthreads();

    const int tr = tid >> 4, tc = tid & 15;
    float acc[4][4] = {};
    #pragma unroll 16
    for (int d = 0; d < DIM; ++d) {
        float4 a = *(const float4*)&xT[d*SP + tr*4];
        float4 b = *(const float4*)&ps[d*SP + tc*4];
        FMA16(acc, a, b)
    }
    #pragma unroll
    for (int i = 0; i < 4; ++i)
        #pragma unroll
        for (int j = 0; j < 4; ++j) acc[i][j] *= DN;

    // diag partial: this thread sums d = tc*4..tc*4+3 for its 4 rows
    float mxr[4], dgr[4];
    #pragma unroll
    for (int i = 0; i < 4; ++i) {
        float s = 0.f;
        #pragma unroll
        for (int dd = 0; dd < 4; ++dd) {
            float xv = xT[(tc*4+dd)*SP + tr*4 + i];
            s += xv * xv;
        }
        float m = fmaxf(fmaxf(acc[i][0], acc[i][1]), fmaxf(acc[i][2], acc[i][3]));
        #pragma unroll
        for (int off = 8; off; off >>= 1) {
            m += 0.f; // keep order stable
            m = fmaxf(m, __shfl_xor_sync(0xffffffffu, m, off));
            s += __shfl_xor_sync(0xffffffffu, s, off);
        }
        mxr[i] = m;
        dgr[i] = 0.5f * DN * DN * s;
    }

    if (IS_Q) {
        #pragma unroll
        for (int i = 0; i < 4; ++i) {
            float4 o;
            o.x = RATIO * (expf(acc[i][0] - dgr[i] - mxr[i]) + EPSV);
            o.y = RATIO * (expf(acc[i][1] - dgr[i] - mxr[i]) + EPSV);
            o.z = RATIO * (expf(acc[i][2] - dgr[i] - mxr[i]) + EPSV);
            o.w = RATIO * (expf(acc[i][3] - dgr[i] - mxr[i]) + EPSV);
            *(float4*)&g_qp[(size_t)(rowBase + tr*4 + i)*MF + tc*4] = o;
        }
    } else {
        #pragma unroll
        for (int i = 0; i < 4; ++i) {
            float4 o = make_float4(acc[i][0], acc[i][1], acc[i][2], acc[i][3]);
            *(float4*)&g_kp[(size_t)(rowBase + tr*4 + i)*MF + tc*4] = o;
            if (tc == 0) g_kdiag[rowBase + tr*4 + i] = dgr[i];
        }
        float lm = fmaxf(fmaxf(mxr[0], mxr[1]), fmaxf(mxr[2], mxr[3]));
        if (tc == 0) wmax[tr] = lm;
        __syncthreads();
        if (tid == 0) {
            float bm = wmax[0];
            #pragma unroll
            for (int r = 1; r < 16; ++r) bm = fmaxf(bm, wmax[r]);
            atomicMaxFloat(&g_bhmax[bh], bm);
        }
    }
}

// ---------------------------------------------------------------------------
// Per-chunk KV: kv[m][d] = sum_j kp[j][m]*v[j][d];  ks[m] = sum_j kp[j][m]
// exp applied inline on kp-dash during smem fill.
// ---------------------------------------------------------------------------
__global__ void chunkkv_kernel(const float* __restrict__ v) {
    __shared__ float k_s[TILE];   // [j][m]
    __shared__ float v_s[TILE];   // [j][d]
    const int tid = threadIdx.x;
    const int bh = blockIdx.x >> 6, c = blockIdx.x & 63;
    const size_t tokBase = (size_t)bh*LEN + (size_t)c*CHK;
    const float mx = g_bhmax[bh];
    const float4* kpp = (const float4*)(g_kp + tokBase*MF);
    const float4* vp  = (const float4*)(v    + tokBase*DIM);

    for (int i4 = tid; i4 < CHK*MF/4; i4 += 256) {
        int r = i4 >> 4, m0 = (i4 & 15) * 4;
        float dg = g_kdiag[tokBase + r];
        float4 kd = kpp[i4];
        float4 e;
        e.x = RATIO * (expf(kd.x - dg - mx) + EPSV);
        e.y = RATIO * (expf(kd.y - dg - mx) + EPSV);
        e.z = RATIO * (expf(kd.z - dg - mx) + EPSV);
        e.w = RATIO * (expf(kd.w - dg - mx) + EPSV);
        *(float4*)&k_s[r*SP + m0] = e;
        *(float4*)&v_s[r*SP + m0] = vp[i4];
    }
    __syncthreads();

    const int tm = tid >> 4, td = tid & 15;
    float acc[4][4] = {};
    #pragma unroll 16
    for (int j = 0; j < CHK; ++j) {
        float4 a = *(const float4*)&k_s[j*SP + tm*4];
        float4 b = *(const float4*)&v_s[j*SP + td*4];
        FMA16(acc, a, b)
    }
    const size_t ob = (size_t)blockIdx.x * MF * DIM;
    #pragma unroll
    for (int i = 0; i < 4; ++i) {
        float4 o = make_float4(acc[i][0], acc[i][1], acc[i][2], acc[i][3]);
        *(float4*)&g_kv[ob + (size_t)(tm*4+i)*DIM + td*4] = o;
    }
    if (tid < MF) {
        float s = 0.f;
        #pragma unroll 16
        for (int j = 0; j < CHK; ++j) s += k_s[j*SP + tid];
        g_ks[(size_t)blockIdx.x * MF + tid] = s;
    }
}

// Exclusive prefix over chunks, one lane per thread. 131072 kv lanes + 2048 ks lanes.
__global__ void scan_kernel() {
    const int gid = blockIdx.x * 256 + threadIdx.x;
    if (blockIdx.x < 512) {
        const int bh = gid / (MF*DIM), e = gid % (MF*DIM);
        size_t base = (size_t)bh*NC*MF*DIM + e;
        float run = 0.f;
        #pragma unroll 8
        for (int c = 0; c < NC; ++c) {
            const size_t idx = base + (size_t)c*MF*DIM;
            const float t = g_kv[idx];
            g_kv[idx] = run;
            run += t;
        }
    } else {
        const int lid = gid - 512*256;      // 0..2047
        const int bh = lid / MF, e = lid % MF;
        size_t base = (size_t)bh*NC*MF + e;
        float run = 0.f;
        #pragma unroll 8
        for (int c = 0; c < NC; ++c) {
            const size_t idx = base + (size_t)c*MF;
            const float t = g_ks[idx];
            g_ks[idx] = run;
            run += t;
        }
    }
}

// ---------------------------------------------------------------------------
// Output: S = Qc Kc^T (causal), out = (S Vc + Qc KVprev) / (rowsum(S) + Qc.KSprev)
// ---------------------------------------------------------------------------
__global__ void attn_kernel(const float* __restrict__ v, float* __restrict__ out) {
    extern __shared__ float sm[];
    float* qT   = sm;              // [m][r]
    float* kT   = qT  + TILE;      // [m][r]
    float* vs   = kT  + TILE;      // [j][d]
    float* ST   = vs  + TILE;      // [j][r]  (scores transposed)
    float* kvp  = ST  + TILE;      // [m][d]
    float* ksp  = kvp + TILE;      // [64]
    float* den4 = ksp + 64;        // [4][64]

    const int tid = threadIdx.x;
    const int bh = blockIdx.x >> 6, c = blockIdx.x & 63;
    const size_t tokBase = (size_t)bh*LEN + (size_t)c*CHK;
    const float mx = g_bhmax[bh];

    const float4* qpp = (const float4*)(g_qp + tokBase*MF);
    const float4* kpp = (const float4*)(g_kp + tokBase*MF);
    const float4* vp  = (const float4*)(v    + tokBase*DIM);
    const float4* kvg = (const float4*)(g_kv + (size_t)blockIdx.x*MF*DIM);

    for (int i4 = tid; i4 < 1024; i4 += 256) {
        int r = i4 >> 4, m0 = (i4 & 15) * 4;
        float4 q4 = qpp[i4];
        qT[(m0+0)*SP + r] = q4.x;
        qT[(m0+1)*SP + r] = q4.y;
        qT[(m0+2)*SP + r] = q4.z;
        qT[(m0+3)*SP + r] = q4.w;
        float dg = g_kdiag[tokBase + r];
        float4 k4 = kpp[i4];
        kT[(m0+0)*SP + r] = RATIO * (expf(k4.x - dg - mx) + EPSV);
        kT[(m0+1)*SP + r] = RATIO * (expf(k4.y - dg - mx) + EPSV);
        kT[(m0+2)*SP + r] = RATIO * (expf(k4.z - dg - mx) + EPSV);
        kT[(m0+3)*SP + r] = RATIO * (expf(k4.w - dg - mx) + EPSV);
        *(float4*)&vs[r*SP + m0]  = vp[i4];
        *(float4*)&kvp[r*SP + m0] = kvg[i4];   // r<->m, m0<->d
    }
    if (tid < 64) ksp[tid] = g_ks[(size_t)blockIdx.x*MF + tid];
    __syncthreads();

    const int tr = tid >> 4, tc = tid & 15;

    // Stage 1: S = Q K^T, masked, stored transposed ST[col][row]
    {
        float acc[4][4] = {};
        #pragma unroll 16
        for (int m = 0; m < MF; ++m) {
            float4 a = *(const float4*)&qT[m*SP + tr*4];
            float4 b = *(const float4*)&kT[m*SP + tc*4];
            FMA16(acc, a, b)
        }
        #pragma unroll
        for (int j = 0; j < 4; ++j)
            #pragma unroll
            for (int i = 0; i < 4; ++i) {
                const int rr = tr*4 + i, cc = tc*4 + j;
                ST[cc*SP + rr] = (cc <= rr) ? acc[i][j] : 0.f;
            }
    }
    __syncthreads();

    // Denominator partials: thread -> (row, quarter)
    {
        const int r = tid & 63, p = tid >> 6;
        float s = 0.f;
        #pragma unroll
        for (int j = p*16; j < p*16 + 16; ++j) s += ST[j*SP + r];
        #pragma unroll
        for (int m = p*16; m < p*16 + 16; ++m) s += qT[m*SP + r] * ksp[m];
        den4[p*64 + r] = s;
    }
    __syncthreads();

    // Stage 2: out = S @ V + Q @ KVprev
    float o[4][4] = {};
    #pragma unroll 16
    for (int j = 0; j < CHK; ++j) {
        float4 a = *(const float4*)&ST[j*SP + tr*4];
        float4 b = *(const float4*)&vs[j*SP + tc*4];
        FMA16(o, a, b)
    }
    #pragma unroll 16
    for (int m = 0; m < MF; ++m) {
        float4 a = *(const float4*)&qT[m*SP + tr*4];
        float4 b = *(const float4*)&kvp[m*SP + tc*4];
        FMA16(o, a, b)
    }

    #pragma unroll
    for (int i = 0; i < 4; ++i) {
        const int r = tr*4 + i;
        const float inv = 1.f / (den4[r] + den4[64+r] + den4[128+r] + den4[192+r]);
        float4 o4 = make_float4(o[i][0]*inv, o[i][1]*inv, o[i][2]*inv, o[i][3]*inv);
        *(float4*)&out[(tokBase + r)*DIM + tc*4] = o4;
    }
}

// ---------------------------------------------------------------------------

extern "C" void kernel_launch(void* const* d_in, const int* in_sizes, int n_in,
                              void* d_out, int out_size) {
    const float* q    = (const float*)d_in[0];
    const float* k    = (const float*)d_in[1];
    const float* v    = (const float*)d_in[2];
    const float* proj = (const float*)d_in[3];
    float* out = (float*)d_out;

    const int ATTN_SMEM = (5*TILE + 64 + 256) * (int)sizeof(float);  // 88320 B
    cudaFuncSetAttribute(attn_kernel, cudaFuncAttributeMaxDynamicSharedMemorySize, ATTN_SMEM);

    init_kernel<<<1, 32>>>();
    feat_kernel<true ><<<BH*LEN/64, 256>>>(q, proj);
    feat_kernel<false><<<BH*LEN/64, 256>>>(k, proj);
    chunkkv_kernel<<<BH*NC, 256>>>(v);
    scan_kernel<<<520, 256>>>();
    attn_kernel<<<BH*NC, 256, ATTN_SMEM>>>(v, out);
}

// round 3
// speedup vs baseline: 2.0967x; 1.0631x over previous
#include <cuda_runtime.h>
#include <math.h>

#define BH   32
#define LEN  4096
#define DIM  64
#define MF   64
#define CHK  64
#define NC   (LEN/CHK)     // 64

#define DN     0.35355339059327373f  // 64^-0.25
#define RATIO  0.125f                // 64^-0.5
#define EPSV   1e-4f

#define SP   68                      // padded smem row stride (floats)
#define TILE (64*SP)                 // 4352 floats

typedef unsigned long long ull;

// Scratch (device globals: allocation-free rule)
__device__ float g_qp[BH*LEN*MF];      // positive features of q
__device__ float g_kp[BH*LEN*MF];      // k dash (raw, exp applied at use)
__device__ float g_kdiag[BH*LEN];      // 0.5*|k|^2*dn^2 per token
__device__ float g_bhmax[BH];          // per-(b,h) max of k dash
__device__ float g_kv[BH*NC*MF*DIM];   // per-chunk KV -> exclusive prefix (in place)
__device__ float g_ks[BH*NC*MF];       // per-chunk K-sum -> exclusive prefix

__device__ __forceinline__ void atomicMaxFloat(float* addr, float val) {
    int* ia = (int*)addr;
    int old = *ia;
    while (__int_as_float(old) < val) {
        int assumed = old;
        old = atomicCAS(ia, assumed, __float_as_int(val));
        if (old == assumed) break;
    }
}

__global__ void init_kernel() {
    if (threadIdx.x < BH) g_bhmax[threadIdx.x] = -INFINITY;
}

// ---- packed fp32x2 helpers (Blackwell FFMA2 path) ----
__device__ __forceinline__ ull pack2(float x) {
    ull r; asm("mov.b64 %0, {%1, %1};" : "=l"(r) : "f"(x)); return r;
}
__device__ __forceinline__ void fma2(ull& d, ull a, ull b) {
    asm("fma.rn.f32x2 %0, %1, %2, %0;" : "+l"(d) : "l"(a), "l"(b));
}
__device__ __forceinline__ float2 unp(ull v) {
    float2 r; asm("mov.b64 {%0, %1}, %2;" : "=f"(r.x), "=f"(r.y) : "l"(v)); return r;
}

// 8x4 micro-step: A (transposed, [k][row]) gives 8 rows as 4 natural f32x2 pairs;
// B gives 4 cols, packed/broadcast. 16 FFMA2 = 32 FMAs per thread per k.
__device__ __forceinline__ void step84(ull acc[4][4], const float* A, const float* B) {
    ulonglong2 a01 = *(const ulonglong2*)(A);
    ulonglong2 a23 = *(const ulonglong2*)(A + 4);
    float4 b = *(const float4*)(B);
    ull b0 = pack2(b.x), b1 = pack2(b.y), b2 = pack2(b.z), b3 = pack2(b.w);
    fma2(acc[0][0], a01.x, b0); fma2(acc[0][1], a01.x, b1); fma2(acc[0][2], a01.x, b2); fma2(acc[0][3], a01.x, b3);
    fma2(acc[1][0], a01.y, b0); fma2(acc[1][1], a01.y, b1); fma2(acc[1][2], a01.y, b2); fma2(acc[1][3], a01.y, b3);
    fma2(acc[2][0], a23.x, b0); fma2(acc[2][1], a23.x, b1); fma2(acc[2][2], a23.x, b2); fma2(acc[2][3], a23.x, b3);
    fma2(acc[3][0], a23.y, b0); fma2(acc[3][1], a23.y, b1); fma2(acc[3][2], a23.y, b2); fma2(acc[3][3], a23.y, b3);
}

// ---------------------------------------------------------------------------
// Feature kernel: 64 rows per block, 128 threads, 8x4 register tile.
// dash = (X @ P) * dn ; diag = 0.5*|x|^2*dn^2
// IS_Q: per-row max -> exp -> g_qp.   else: raw dash -> g_kp, diag, atomic bh max.
// ---------------------------------------------------------------------------
template<bool IS_Q>
__global__ void feat_kernel(const float* __restrict__ x, const float* __restrict__ proj) {
    __shared__ float xT[TILE];     // [d][row]
    __shared__ float ps[TILE];     // [d][m]
    __shared__ float diag_s[64];
    __shared__ float wmax[8];

    const int tid = threadIdx.x;
    const int rowBase = blockIdx.x * 64;
    const int bh = blockIdx.x >> 6;

    for (int i4 = tid; i4 < DIM*MF/4; i4 += 128) {
        float4 p = ((const float4*)proj)[i4];
        int d = i4 >> 4, m0 = (i4 & 15) * 4;
        *(float4*)&ps[d*SP + m0] = p;
    }
    {
        const float4* xg = (const float4*)(x + (size_t)rowBase * DIM);
        for (int i4 = tid; i4 < 64*DIM/4; i4 += 128) {
            float4 xv = xg[i4];
            int r = i4 >> 4, d0 = (i4 & 15) * 4;
            xT[(d0+0)*SP + r] = xv.x;
            xT[(d0+1)*SP + r] = xv.y;
            xT[(d0+2)*SP + r] = xv.z;
            xT[(d0+3)*SP + r] = xv.w;
        }
    }
    __syncthreads();

    if (tid < 64) {   // per-row diag
        float s = 0.f;
        #pragma unroll 16
        for (int d = 0; d < DIM; ++d) { float xv = xT[d*SP + tid]; s += xv*xv; }
        diag_s[tid] = 0.5f * DN * DN * s;
    }

    const int tr = tid >> 4, tc = tid & 15;
    ull acc[4][4] = {};
    #pragma unroll 8
    for (int d = 0; d < DIM; ++d)
        step84(acc, &xT[d*SP + tr*8], &ps[d*SP + tc*4]);
    __syncthreads();   // diag_s ready

    float f[8][4];
    #pragma unroll
    for (int rp = 0; rp < 4; ++rp)
        #pragma unroll
        for (int j = 0; j < 4; ++j) {
            float2 vv = unp(acc[rp][j]);
            f[2*rp][j]   = vv.x * DN;
            f[2*rp+1][j] = vv.y * DN;
        }

    if (IS_Q) {
        #pragma unroll
        for (int rr = 0; rr < 8; ++rr) {
            const int r = tr*8 + rr;
            float m = fmaxf(fmaxf(f[rr][0], f[rr][1]), fmaxf(f[rr][2], f[rr][3]));
            #pragma unroll
            for (int off = 8; off; off >>= 1)
                m = fmaxf(m, __shfl_xor_sync(0xffffffffu, m, off));
            const float sub = diag_s[r] + m;
            float4 o;
            o.x = RATIO * (expf(f[rr][0] - sub) + EPSV);
            o.y = RATIO * (expf(f[rr][1] - sub) + EPSV);
            o.z = RATIO * (expf(f[rr][2] - sub) + EPSV);
            o.w = RATIO * (expf(f[rr][3] - sub) + EPSV);
            *(float4*)&g_qp[(size_t)(rowBase + r)*MF + tc*4] = o;
        }
    } else {
        float bm = -INFINITY;
        #pragma unroll
        for (int rr = 0; rr < 8; ++rr) {
            const int r = tr*8 + rr;
            *(float4*)&g_kp[(size_t)(rowBase + r)*MF + tc*4] =
                make_float4(f[rr][0], f[rr][1], f[rr][2], f[rr][3]);
            bm = fmaxf(bm, fmaxf(fmaxf(f[rr][0], f[rr][1]), fmaxf(f[rr][2], f[rr][3])));
        }
        if (tid < 64) g_kdiag[rowBase + tid] = diag_s[tid];
        #pragma unroll
        for (int off = 8; off; off >>= 1)
            bm = fmaxf(bm, __shfl_xor_sync(0xffffffffu, bm, off));
        if (tc == 0) wmax[tr] = bm;
        __syncthreads();
        if (tid == 0) {
            float b2 = wmax[0];
            #pragma unroll
            for (int i = 1; i < 8; ++i) b2 = fmaxf(b2, wmax[i]);
            atomicMaxFloat(&g_bhmax[bh], b2);
        }
    }
}

// ---------------------------------------------------------------------------
// Per-chunk KV: kv[m][d] = sum_j kp[j][m]*v[j][d];  ks[m] = sum_j kp[j][m]
// exp applied inline on kp-dash during smem fill. 128 threads, 8x4 tiles.
// ---------------------------------------------------------------------------
__global__ void chunkkv_kernel(const float* __restrict__ v) {
    __shared__ float k_s[TILE];   // [j][m]
    __shared__ float v_s[TILE];   // [j][d]
    const int tid = threadIdx.x;
    const int bh = blockIdx.x >> 6;
    const size_t tokBase = (size_t)blockIdx.x * CHK;
    const float mx = g_bhmax[bh];
    const float4* kpp = (const float4*)(g_kp + tokBase*MF);
    const float4* vp  = (const float4*)(v    + tokBase*DIM);

    for (int i4 = tid; i4 < 1024; i4 += 128) {
        int r = i4 >> 4, m0 = (i4 & 15) * 4;
        float dg = g_kdiag[tokBase + r];
        float4 kd = kpp[i4], e;
        e.x = RATIO * (expf(kd.x - dg - mx) + EPSV);
        e.y = RATIO * (expf(kd.y - dg - mx) + EPSV);
        e.z = RATIO * (expf(kd.z - dg - mx) + EPSV);
        e.w = RATIO * (expf(kd.w - dg - mx) + EPSV);
        *(float4*)&k_s[r*SP + m0] = e;
        *(float4*)&v_s[r*SP + m0] = vp[i4];
    }
    __syncthreads();

    const int tm = tid >> 4, td = tid & 15;
    ull acc[4][4] = {};
    #pragma unroll 8
    for (int j = 0; j < CHK; ++j)
        step84(acc, &k_s[j*SP + tm*8], &v_s[j*SP + td*4]);

    const size_t ob = (size_t)blockIdx.x * MF * DIM;
    #pragma unroll
    for (int rp = 0; rp < 4; ++rp) {
        float2 c0 = unp(acc[rp][0]), c1 = unp(acc[rp][1]), c2 = unp(acc[rp][2]), c3 = unp(acc[rp][3]);
        const int m0 = tm*8 + 2*rp;
        *(float4*)&g_kv[ob + (size_t)(m0  )*DIM + td*4] = make_float4(c0.x, c1.x, c2.x, c3.x);
        *(float4*)&g_kv[ob + (size_t)(m0+1)*DIM + td*4] = make_float4(c0.y, c1.y, c2.y, c3.y);
    }
    if (tid < 64) {
        float s = 0.f;
        #pragma unroll 8
        for (int j = 0; j < CHK; ++j) s += k_s[j*SP + tid];
        g_ks[(size_t)blockIdx.x * MF + tid] = s;
    }
}

// Exclusive prefix over chunks, one lane per thread.
__global__ void scan_kernel() {
    const int gid = blockIdx.x * 256 + threadIdx.x;
    if (blockIdx.x < 512) {
        const int bh = gid / (MF*DIM), e = gid % (MF*DIM);
        size_t base = (size_t)bh*NC*MF*DIM + e;
        float run = 0.f;
        #pragma unroll 8
        for (int c = 0; c < NC; ++c) {
            const size_t idx = base + (size_t)c*MF*DIM;
            const float t = g_kv[idx];
            g_kv[idx] = run;
            run += t;
        }
    } else {
        const int lid = gid - 512*256;
        const int bh = lid / MF, e = lid % MF;
        size_t base = (size_t)bh*NC*MF + e;
        float run = 0.f;
        #pragma unroll 8
        for (int c = 0; c < NC; ++c) {
            const size_t idx = base + (size_t)c*MF;
            const float t = g_ks[idx];
            g_ks[idx] = run;
            run += t;
        }
    }
}

// ---------------------------------------------------------------------------
// Output: S = Qc Kc^T (causal), out = (S Vc + Qc KVprev) / (rowsum(S) + Qc.KSprev)
// 128 threads, 8x4 tiles, FFMA2.
// ---------------------------------------------------------------------------
__global__ void attn_kernel(const float* __restrict__ v, float* __restrict__ out) {
    extern __shared__ float sm[];
    float* qT   = sm;              // [m][r]
    float* kT   = qT  + TILE;      // [m][c]
    float* vs   = kT  + TILE;      // [j][d]
    float* ST   = vs  + TILE;      // [j][r]  (scores transposed)
    float* kvp  = ST  + TILE;      // [m][d]
    float* ksp  = kvp + TILE;      // [64]
    float* denA = ksp + 64;        // [64]
    float* denB = denA + 64;       // [64]

    const int tid = threadIdx.x;
    const int bh = blockIdx.x >> 6;
    const size_t tokBase = (size_t)blockIdx.x * CHK;
    const float mx = g_bhmax[bh];

    const float4* qpp = (const float4*)(g_qp + tokBase*MF);
    const float4* kpp = (const float4*)(g_kp + tokBase*MF);
    const float4* vp  = (const float4*)(v    + tokBase*DIM);
    const float4* kvg = (const float4*)(g_kv + (size_t)blockIdx.x*MF*DIM);

    for (int i4 = tid; i4 < 1024; i4 += 128) {
        int r = i4 >> 4, m0 = (i4 & 15) * 4;
        float4 q4 = qpp[i4];
        qT[(m0+0)*SP + r] = q4.x;
        qT[(m0+1)*SP + r] = q4.y;
        qT[(m0+2)*SP + r] = q4.z;
        qT[(m0+3)*SP + r] = q4.w;
        float dg = g_kdiag[tokBase + r];
        float4 k4 = kpp[i4];
        kT[(m0+0)*SP + r] = RATIO * (expf(k4.x - dg - mx) + EPSV);
        kT[(m0+1)*SP + r] = RATIO * (expf(k4.y - dg - mx) + EPSV);
        kT[(m0+2)*SP + r] = RATIO * (expf(k4.z - dg - mx) + EPSV);
        kT[(m0+3)*SP + r] = RATIO * (expf(k4.w - dg - mx) + EPSV);
        *(float4*)&vs[r*SP + m0]  = vp[i4];
        *(float4*)&kvp[r*SP + m0] = kvg[i4];
    }
    if (tid < 64) ksp[tid] = g_ks[(size_t)blockIdx.x*MF + tid];
    __syncthreads();

    const int tr = tid >> 4, tc = tid & 15;

    // Stage 1: S = Q K^T, masked, stored transposed ST[col][row]
    {
        ull acc[4][4] = {};
        #pragma unroll 8
        for (int m = 0; m < MF; ++m)
            step84(acc, &qT[m*SP + tr*8], &kT[m*SP + tc*4]);
        #pragma unroll
        for (int rp = 0; rp < 4; ++rp)
            #pragma unroll
            for (int j = 0; j < 4; ++j) {
                float2 vv = unp(acc[rp][j]);
                const int c = tc*4 + j, r0 = tr*8 + 2*rp;
                ST[c*SP + r0]     = (c <= r0)     ? vv.x : 0.f;
                ST[c*SP + r0 + 1] = (c <= r0 + 1) ? vv.y : 0.f;
            }
    }
    __syncthreads();

    // Denominator partials
    if (tid < 64) {
        float s = 0.f;
        #pragma unroll 8
        for (int j = 0; j < CHK; ++j) s += ST[j*SP + tid];
        denA[tid] = s;
    } else {
        const int r = tid - 64;
        float s = 0.f;
        #pragma unroll 8
        for (int m = 0; m < MF; ++m) s += qT[m*SP + r] * ksp[m];
        denB[r] = s;
    }

    // Stage 2+3: out = S @ V + Q @ KVprev
    ull o[4][4] = {};
    #pragma unroll 8
    for (int j = 0; j < CHK; ++j)
        step84(o, &ST[j*SP + tr*8], &vs[j*SP + tc*4]);
    #pragma unroll 8
    for (int m = 0; m < MF; ++m)
        step84(o, &qT[m*SP + tr*8], &kvp[m*SP + tc*4]);
    __syncthreads();   // denA/denB ready for all threads

    #pragma unroll
    for (int rp = 0; rp < 4; ++rp) {
        const int r0 = tr*8 + 2*rp;
        float2 c0 = unp(o[rp][0]), c1 = unp(o[rp][1]), c2 = unp(o[rp][2]), c3 = unp(o[rp][3]);
        const float inv0 = 1.f / (denA[r0]   + denB[r0]);
        const float inv1 = 1.f / (denA[r0+1] + denB[r0+1]);
        *(float4*)&out[(tokBase + r0  )*DIM + tc*4] = make_float4(c0.x*inv0, c1.x*inv0, c2.x*inv0, c3.x*inv0);
        *(float4*)&out[(tokBase + r0+1)*DIM + tc*4] = make_float4(c0.y*inv1, c1.y*inv1, c2.y*inv1, c3.y*inv1);
    }
}

// ---------------------------------------------------------------------------

extern "C" void kernel_launch(void* const* d_in, const int* in_sizes, int n_in,
                              void* d_out, int out_size) {
    const float* q    = (const float*)d_in[0];
    const float* k    = (const float*)d_in[1];
    const float* v    = (const float*)d_in[2];
    const float* proj = (const float*)d_in[3];
    float* out = (float*)d_out;

    const int ATTN_SMEM = (5*TILE + 64 + 64 + 64) * (int)sizeof(float);  // 87808 B
    cudaFuncSetAttribute(attn_kernel, cudaFuncAttributeMaxDynamicSharedMemorySize, ATTN_SMEM);

    init_kernel<<<1, 32>>>();
    feat_kernel<true ><<<BH*LEN/64, 128>>>(q, proj);
    feat_kernel<false><<<BH*LEN/64, 128>>>(k, proj);
    chunkkv_kernel<<<BH*NC, 128>>>(v);
    scan_kernel<<<520, 256>>>();
    attn_kernel<<<BH*NC, 128, ATTN_SMEM>>>(v, out);
}

// round 5
// speedup vs baseline: 2.1864x; 1.0428x over previous
#include <cuda_runtime.h>
#include <cstdint>
#include <math.h>

#define BH   32
#define LEN  4096
#define DIM  64
#define MF   64
#define CHK  128
#define NC   (LEN/CHK)     // 32

#define DN     0.35355339059327373f  // 64^-0.25
#define RATIO  0.125f                // 64^-0.5
#define EPSV   1e-4f

#define SP    68
#define FTILE (64*SP)

typedef unsigned long long ull;

// Scratch (device globals: allocation-free rule)
__device__ float g_qp[BH*LEN*MF];      // positive features of q
__device__ float g_kp[BH*LEN*MF];      // k dash (raw, exp applied at use)
__device__ float g_kdiag[BH*LEN];      // 0.5*|k|^2*dn^2 per token
__device__ float g_bhmax[BH];          // per-(b,h) max of k dash
__device__ float g_kv[BH*NC*MF*DIM];   // per-chunk KV^T [bh][c][d][m] -> exclusive prefix
__device__ float g_ks[BH*NC*MF];       // per-chunk K-sum -> exclusive prefix

// ==================== helpers ====================

__device__ __forceinline__ void atomicMaxFloat(float* addr, float val) {
    int* ia = (int*)addr;
    int old = *ia;
    while (__int_as_float(old) < val) {
        int assumed = old;
        old = atomicCAS(ia, assumed, __float_as_int(val));
        if (old == assumed) break;
    }
}

__global__ void init_kernel() {
    if (threadIdx.x < BH) g_bhmax[threadIdx.x] = -INFINITY;
}

__device__ __forceinline__ ull pack2(float x) {
    ull r; asm("mov.b64 %0, {%1, %1};" : "=l"(r) : "f"(x)); return r;
}
__device__ __forceinline__ void fma2(ull& d, ull a, ull b) {
    asm("fma.rn.f32x2 %0, %1, %2, %0;" : "+l"(d) : "l"(a), "l"(b));
}
__device__ __forceinline__ float2 unp(ull v) {
    float2 r; asm("mov.b64 {%0, %1}, %2;" : "=f"(r.x), "=f"(r.y) : "l"(v)); return r;
}
__device__ __forceinline__ void step84(ull acc[4][4], const float* A, const float* B) {
    ulonglong2 a01 = *(const ulonglong2*)(A);
    ulonglong2 a23 = *(const ulonglong2*)(A + 4);
    float4 b = *(const float4*)(B);
    ull b0 = pack2(b.x), b1 = pack2(b.y), b2 = pack2(b.z), b3 = pack2(b.w);
    fma2(acc[0][0], a01.x, b0); fma2(acc[0][1], a01.x, b1); fma2(acc[0][2], a01.x, b2); fma2(acc[0][3], a01.x, b3);
    fma2(acc[1][0], a01.y, b0); fma2(acc[1][1], a01.y, b1); fma2(acc[1][2], a01.y, b2); fma2(acc[1][3], a01.y, b3);
    fma2(acc[2][0], a23.x, b0); fma2(acc[2][1], a23.x, b1); fma2(acc[2][2], a23.x, b2); fma2(acc[2][3], a23.x, b3);
    fma2(acc[3][0], a23.y, b0); fma2(acc[3][1], a23.y, b1); fma2(acc[3][2], a23.y, b2); fma2(acc[3][3], a23.y, b3);
}

// tf32 convert (keeps fp32 bit layout, low mantissa bits rounded away)
__device__ __forceinline__ uint32_t tf32c(float f) {
    uint32_t r; asm("cvt.rna.tf32.f32 %0, %1;" : "=r"(r) : "f"(f)); return r;
}

// mma.sync m16n8k8 tf32: D += A*B (D,C fp32; A 4 regs; B 2 regs)
__device__ __forceinline__ void mma1688(float* d, const uint32_t* a, uint32_t b0, uint32_t b1) {
    asm volatile(
        "mma.sync.aligned.m16n8k8.row.col.f32.tf32.tf32.f32 "
        "{%0,%1,%2,%3}, {%4,%5,%6,%7}, {%8,%9}, {%0,%1,%2,%3};"
        : "+f"(d[0]), "+f"(d[1]), "+f"(d[2]), "+f"(d[3])
        : "r"(a[0]), "r"(a[1]), "r"(a[2]), "r"(a[3]), "r"(b0), "r"(b1));
}

// ---------------------------------------------------------------------------
// Feature kernel (unchanged, FFMA2): 64 rows/block, 128 threads.
// ---------------------------------------------------------------------------
template<bool IS_Q>
__global__ void feat_kernel(const float* __restrict__ x, const float* __restrict__ proj) {
    __shared__ float xT[FTILE];     // [d][row]
    __shared__ float ps[FTILE];     // [d][m]
    __shared__ float diag_s[64];
    __shared__ float wmax[8];

    const int tid = threadIdx.x;
    const int rowBase = blockIdx.x * 64;
    const int bh = blockIdx.x >> 6;

    for (int i4 = tid; i4 < DIM*MF/4; i4 += 128) {
        float4 p = ((const float4*)proj)[i4];
        int d = i4 >> 4, m0 = (i4 & 15) * 4;
        *(float4*)&ps[d*SP + m0] = p;
    }
    {
        const float4* xg = (const float4*)(x + (size_t)rowBase * DIM);
        for (int i4 = tid; i4 < 64*DIM/4; i4 += 128) {
            float4 xv = xg[i4];
            int r = i4 >> 4, d0 = (i4 & 15) * 4;
            xT[(d0+0)*SP + r] = xv.x;
            xT[(d0+1)*SP + r] = xv.y;
            xT[(d0+2)*SP + r] = xv.z;
            xT[(d0+3)*SP + r] = xv.w;
        }
    }
    __syncthreads();

    if (tid < 64) {
        float s = 0.f;
        #pragma unroll 16
        for (int d = 0; d < DIM; ++d) { float xv = xT[d*SP + tid]; s += xv*xv; }
        diag_s[tid] = 0.5f * DN * DN * s;
    }

    const int tr = tid >> 4, tc = tid & 15;
    ull acc[4][4] = {};
    #pragma unroll 8
    for (int d = 0; d < DIM; ++d)
        step84(acc, &xT[d*SP + tr*8], &ps[d*SP + tc*4]);
    __syncthreads();

    float f[8][4];
    #pragma unroll
    for (int rp = 0; rp < 4; ++rp)
        #pragma unroll
        for (int j = 0; j < 4; ++j) {
            float2 vv = unp(acc[rp][j]);
            f[2*rp][j]   = vv.x * DN;
            f[2*rp+1][j] = vv.y * DN;
        }

    if (IS_Q) {
        #pragma unroll
        for (int rr = 0; rr < 8; ++rr) {
            const int r = tr*8 + rr;
            float m = fmaxf(fmaxf(f[rr][0], f[rr][1]), fmaxf(f[rr][2], f[rr][3]));
            #pragma unroll
            for (int off = 8; off; off >>= 1)
                m = fmaxf(m, __shfl_xor_sync(0xffffffffu, m, off));
            const float sub = diag_s[r] + m;
            float4 o;
            o.x = RATIO * (expf(f[rr][0] - sub) + EPSV);
            o.y = RATIO * (expf(f[rr][1] - sub) + EPSV);
            o.z = RATIO * (expf(f[rr][2] - sub) + EPSV);
            o.w = RATIO * (expf(f[rr][3] - sub) + EPSV);
            *(float4*)&g_qp[(size_t)(rowBase + r)*MF + tc*4] = o;
        }
    } else {
        float bm = -INFINITY;
        #pragma unroll
        for (int rr = 0; rr < 8; ++rr) {
            const int r = tr*8 + rr;
            *(float4*)&g_kp[(size_t)(rowBase + r)*MF + tc*4] =
                make_float4(f[rr][0], f[rr][1], f[rr][2], f[rr][3]);
            bm = fmaxf(bm, fmaxf(fmaxf(f[rr][0], f[rr][1]), fmaxf(f[rr][2], f[rr][3])));
        }
        if (tid < 64) g_kdiag[rowBase + tid] = diag_s[tid];
        #pragma unroll
        for (int off = 8; off; off >>= 1)
            bm = fmaxf(bm, __shfl_xor_sync(0xffffffffu, bm, off));
        if (tc == 0) wmax[tr] = bm;
        __syncthreads();
        if (tid == 0) {
            float b2 = wmax[0];
            #pragma unroll
            for (int i = 1; i < 8; ++i) b2 = fmaxf(b2, wmax[i]);
            atomicMaxFloat(&g_bhmax[bh], b2);
        }
    }
}

// ---------------------------------------------------------------------------
// Per-chunk KV^T: kvT[d][m] = sum_j V[j][d]*Kp[j][m]; ks[m] = sum_j Kp[j][m]
// CHK=128 tokens per block. 128 threads, FFMA2.
// ---------------------------------------------------------------------------
__global__ void chunkkv_kernel(const float* __restrict__ v) {
    extern __shared__ char dsm[];
    float* k_s = (float*)dsm;               // [128][SP]
    float* v_s = (float*)dsm + 128*SP;      // [128][SP]
    const int tid = threadIdx.x;
    const int bh = blockIdx.x >> 5;
    const size_t tokBase = (size_t)blockIdx.x * CHK;
    const float mx = g_bhmax[bh];
    const float4* kpp = (const float4*)(g_kp + tokBase*MF);
    const float4* vp  = (const float4*)(v    + tokBase*DIM);

    for (int i4 = tid; i4 < 2048; i4 += 128) {
        int r = i4 >> 4, m0 = (i4 & 15) * 4;
        float dg = g_kdiag[tokBase + r];
        float4 kd = kpp[i4], e;
        e.x = RATIO * (expf(kd.x - dg - mx) + EPSV);
        e.y = RATIO * (expf(kd.y - dg - mx) + EPSV);
        e.z = RATIO * (expf(kd.z - dg - mx) + EPSV);
        e.w = RATIO * (expf(kd.w - dg - mx) + EPSV);
        *(float4*)&k_s[r*SP + m0] = e;
        *(float4*)&v_s[r*SP + m0] = vp[i4];
    }
    __syncthreads();

    const int td8 = tid >> 4, tm4 = tid & 15;
    ull acc[4][4] = {};
    #pragma unroll 8
    for (int j = 0; j < CHK; ++j)
        step84(acc, &v_s[j*SP + td8*8], &k_s[j*SP + tm4*4]);

    const size_t ob = (size_t)blockIdx.x * MF * DIM;
    #pragma unroll
    for (int rp = 0; rp < 4; ++rp) {
        float2 c0 = unp(acc[rp][0]), c1 = unp(acc[rp][1]), c2 = unp(acc[rp][2]), c3 = unp(acc[rp][3]);
        const int d0 = td8*8 + 2*rp;
        *(float4*)&g_kv[ob + (size_t)(d0  )*MF + tm4*4] = make_float4(c0.x, c1.x, c2.x, c3.x);
        *(float4*)&g_kv[ob + (size_t)(d0+1)*MF + tm4*4] = make_float4(c0.y, c1.y, c2.y, c3.y);
    }
    if (tid < 64) {
        float s = 0.f;
        #pragma unroll 8
        for (int j = 0; j < CHK; ++j) s += k_s[j*SP + tid];
        g_ks[(size_t)blockIdx.x * MF + tid] = s;
    }
}

// Exclusive prefix over 32 chunks, one lane per thread.
__global__ void scan_kernel() {
    const int gid = blockIdx.x * 256 + threadIdx.x;
    if (blockIdx.x < 512) {
        const int bh = gid >> 12, e = gid & 4095;
        size_t base = (size_t)bh*NC*MF*DIM + e;
        float run = 0.f;
        #pragma unroll 8
        for (int c = 0; c < NC; ++c) {
            const size_t idx = base + (size_t)c*MF*DIM;
            const float t = g_kv[idx];
            g_kv[idx] = run;
            run += t;
        }
    } else {
        const int lid = gid - 512*256;
        const int bh = lid >> 6, e = lid & 63;
        size_t base = (size_t)bh*NC*MF + e;
        float run = 0.f;
        #pragma unroll 8
        for (int c = 0; c < NC; ++c) {
            const size_t idx = base + (size_t)c*MF;
            const float t = g_ks[idx];
            g_ks[idx] = run;
            run += t;
        }
    }
}

// ---------------------------------------------------------------------------
// attn via mma.sync tf32 (m16n8k8), 256 threads = 8 warps, CHK=128.
// Warp w owns rows r0=w*16..r0+15 exclusively after staging (no block syncs).
//   S = Q K^T (causal n-tile skip), masked, rowsum in regs, masked S -> Ss (tf32)
//   D = Q KVprev^T + S V ; out = D / (rowsum + q.ksprev)
// SMEM (uint32 tf32 bit patterns unless noted):
//   Qs[128][68], Ks[128][68], Vs[128][68], KVT[64][68], Ss[128][132], ksum f32[64]
// ---------------------------------------------------------------------------
#define QS_OFF   0
#define KS_OFF   34816
#define VS_OFF   69632
#define KVT_OFF  104448
#define SS_OFF   121856
#define KSUM_OFF 189440
#define ATTN_SMEM 189696

__global__ void __launch_bounds__(256, 1)
attn_kernel(const float* __restrict__ v, float* __restrict__ out) {
    extern __shared__ char smem[];
    uint32_t* Qs   = (uint32_t*)(smem + QS_OFF);
    uint32_t* Ks   = (uint32_t*)(smem + KS_OFF);
    uint32_t* Vs   = (uint32_t*)(smem + VS_OFF);
    uint32_t* KVT  = (uint32_t*)(smem + KVT_OFF);
    uint32_t* Ss   = (uint32_t*)(smem + SS_OFF);
    float*    ksum = (float*)(smem + KSUM_OFF);

    const int tid = threadIdx.x, wid = tid >> 5, lane = tid & 31;
    const int g = lane >> 2, t = lane & 3;
    const int bh = blockIdx.x >> 5;
    const size_t tokBase = (size_t)blockIdx.x * CHK;
    const float mx = g_bhmax[bh];

    const float4* qpp = (const float4*)(g_qp + tokBase*MF);
    const float4* kpp = (const float4*)(g_kp + tokBase*MF);
    const float4* vpp = (const float4*)(v    + tokBase*DIM);
    const float4* kvp = (const float4*)(g_kv + (size_t)blockIdx.x*MF*DIM);

    for (int i4 = tid; i4 < 2048; i4 += 256) {
        const int r = i4 >> 4, c0 = (i4 & 15) * 4;
        float4 q4 = qpp[i4];
        Qs[r*68 + c0 + 0] = tf32c(q4.x);
        Qs[r*68 + c0 + 1] = tf32c(q4.y);
        Qs[r*68 + c0 + 2] = tf32c(q4.z);
        Qs[r*68 + c0 + 3] = tf32c(q4.w);
        const float dg = g_kdiag[tokBase + r];
        float4 kd = kpp[i4];
        Ks[r*68 + c0 + 0] = tf32c(RATIO * (expf(kd.x - dg - mx) + EPSV));
        Ks[r*68 + c0 + 1] = tf32c(RATIO * (expf(kd.y - dg - mx) + EPSV));
        Ks[r*68 + c0 + 2] = tf32c(RATIO * (expf(kd.z - dg - mx) + EPSV));
        Ks[r*68 + c0 + 3] = tf32c(RATIO * (expf(kd.w - dg - mx) + EPSV));
        float4 v4 = vpp[i4];
        Vs[r*68 + c0 + 0] = tf32c(v4.x);
        Vs[r*68 + c0 + 1] = tf32c(v4.y);
        Vs[r*68 + c0 + 2] = tf32c(v4.z);
        Vs[r*68 + c0 + 3] = tf32c(v4.w);
    }
    for (int i4 = tid; i4 < 1024; i4 += 256) {
        const int d = i4 >> 4, m0 = (i4 & 15) * 4;
        float4 kv4 = kvp[i4];
        KVT[d*68 + m0 + 0] = tf32c(kv4.x);
        KVT[d*68 + m0 + 1] = tf32c(kv4.y);
        KVT[d*68 + m0 + 2] = tf32c(kv4.z);
        KVT[d*68 + m0 + 3] = tf32c(kv4.w);
    }
    if (tid < 64) ksum[tid] = g_ks[(size_t)blockIdx.x*MF + tid];
    __syncthreads();

    const int r0 = wid * 16;
    const int ra = r0 + g, rb = ra + 8;

    // preload Q A-fragments for all 8 k-tiles (k = features 0..63)
    uint32_t qa[8][4];
    #pragma unroll
    for (int k = 0; k < 8; ++k) {
        qa[k][0] = Qs[ra*68 + k*8 + t];
        qa[k][1] = Qs[rb*68 + k*8 + t];
        qa[k][2] = Qs[ra*68 + k*8 + t + 4];
        qa[k][3] = Qs[rb*68 + k*8 + t + 4];
    }

    // ---- Stage 1: S = Q K^T over causal n-tiles; mask; rowsum; store tf32 ----
    float rs0 = 0.f, rs1 = 0.f;
    const int ntiles = (r0 >> 3) + 2;
    for (int n0 = 0; n0 < ntiles; ++n0) {
        float d4[4] = {0.f, 0.f, 0.f, 0.f};
        const int jrow = n0*8 + g;
        #pragma unroll
        for (int k = 0; k < 8; ++k) {
            uint32_t b0 = Ks[jrow*68 + k*8 + t];
            uint32_t b1 = Ks[jrow*68 + k*8 + t + 4];
            mma1688(d4, qa[k], b0, b1);
        }
        const int ca = n0*8 + 2*t;
        d4[0] = (ca     <= ra) ? d4[0] : 0.f;
        d4[1] = (ca + 1 <= ra) ? d4[1] : 0.f;
        d4[2] = (ca     <= rb) ? d4[2] : 0.f;
        d4[3] = (ca + 1 <= rb) ? d4[3] : 0.f;
        rs0 += d4[0] + d4[1];
        rs1 += d4[2] + d4[3];
        *(uint2*)&Ss[ra*132 + ca] = make_uint2(tf32c(d4[0]), tf32c(d4[1]));
        *(uint2*)&Ss[rb*132 + ca] = make_uint2(tf32c(d4[2]), tf32c(d4[3]));
    }
    // den += q . ks_prev (partial over m = t*16..t*16+15, completed by quad reduce)
    #pragma unroll
    for (int m = 0; m < 16; ++m) {
        const int mm = t*16 + m;
        const float ks = ksum[mm];
        rs0 += __uint_as_float(Qs[ra*68 + mm]) * ks;
        rs1 += __uint_as_float(Qs[rb*68 + mm]) * ks;
    }
    rs0 += __shfl_xor_sync(0xffffffffu, rs0, 1);
    rs0 += __shfl_xor_sync(0xffffffffu, rs0, 2);
    rs1 += __shfl_xor_sync(0xffffffffu, rs1, 1);
    rs1 += __shfl_xor_sync(0xffffffffu, rs1, 2);
    const float inva = 1.f / rs0, invb = 1.f / rs1;

    // ---- Stage 2: D = Q KVprev^T + S V ----
    float D[8][4] = {};
    #pragma unroll
    for (int n0 = 0; n0 < 8; ++n0) {
        const int drow = n0*8 + g;
        #pragma unroll
        for (int k = 0; k < 8; ++k) {
            uint32_t b0 = KVT[drow*68 + k*8 + t];
            uint32_t b1 = KVT[drow*68 + k*8 + t + 4];
            mma1688(D[n0], qa[k], b0, b1);
        }
    }
    const int ktiles = (r0 >> 3) + 2;
    for (int kt = 0; kt < ktiles; ++kt) {
        uint32_t sa[4];
        sa[0] = Ss[ra*132 + kt*8 + t];
        sa[1] = Ss[rb*132 + kt*8 + t];
        sa[2] = Ss[ra*132 + kt*8 + t + 4];
        sa[3] = Ss[rb*132 + kt*8 + t + 4];
        const int j0 = kt*8 + t;
        #pragma unroll
        for (int n0 = 0; n0 < 8; ++n0) {
            uint32_t b0 = Vs[(j0    )*68 + n0*8 + g];
            uint32_t b1 = Vs[(j0 + 4)*68 + n0*8 + g];
            mma1688(D[n0], sa, b0, b1);
        }
    }

    float* orow_a = out + (tokBase + ra)*DIM;
    float* orow_b = out + (tokBase + rb)*DIM;
    #pragma unroll
    for (int n0 = 0; n0 < 8; ++n0) {
        *(float2*)&orow_a[n0*8 + 2*t] = make_float2(D[n0][0]*inva, D[n0][1]*inva);
        *(float2*)&orow_b[n0*8 + 2*t] = make_float2(D[n0][2]*invb, D[n0][3]*invb);
    }
}

// ---------------------------------------------------------------------------

#define CKV_SMEM (2*128*SP*4)   // 69632

extern "C" void kernel_launch(void* const* d_in, const int* in_sizes, int n_in,
                              void* d_out, int out_size) {
    const float* q    = (const float*)d_in[0];
    const float* k    = (const float*)d_in[1];
    const float* v    = (const float*)d_in[2];
    const float* proj = (const float*)d_in[3];
    float* out = (float*)d_out;

    cudaFuncSetAttribute(chunkkv_kernel, cudaFuncAttributeMaxDynamicSharedMemorySize, CKV_SMEM);
    cudaFuncSetAttribute(attn_kernel,    cudaFuncAttributeMaxDynamicSharedMemorySize, ATTN_SMEM);

    init_kernel<<<1, 32>>>();
    feat_kernel<true ><<<BH*LEN/64, 128>>>(q, proj);
    feat_kernel<false><<<BH*LEN/64, 128>>>(k, proj);
    chunkkv_kernel<<<BH*NC, 128, CKV_SMEM>>>(v);
    scan_kernel<<<520, 256>>>();
    attn_kernel<<<BH*NC, 256, ATTN_SMEM>>>(v, out);
}